// round 16
// baseline (speedup 1.0000x reference)
#include <cuda_runtime.h>
#include <cstdint>

#define NN 2048
#define NE 65536
#define NVIEWS 6
#define C 32

typedef unsigned long long ull;
typedef unsigned int uint32;

// ---- scratch. Invariant: g_agg == 0, g_cnt == 0 at entry of kernel_launch. ----
__device__ float g_agg[NN * C];
__device__ int   g_cnt[NN];
__device__ float g_inv[NN];
__device__ float g_h1[NN * C];
__device__ float g_h2[NN * C];
__device__ float g_h3[NN * C];

// ---- f32x2 helpers (CBT) ----
__device__ __forceinline__ ull pk(float lo, float hi) {
    ull r; asm("mov.b64 %0, {%1,%2};" : "=l"(r) : "f"(lo), "f"(hi)); return r;
}
__device__ __forceinline__ void upk(ull v, float& lo, float& hi) {
    asm("mov.b64 {%0,%1}, %2;" : "=f"(lo), "=f"(hi) : "l"(v));
}
__device__ __forceinline__ ull add2(ull a, ull b) {
    ull d; asm("add.rn.f32x2 %0,%1,%2;" : "=l"(d) : "l"(a), "l"(b)); return d;
}
#define ABSMASK 0x7FFFFFFF7FFFFFFFULL

// tf32 truncation: keep top 10 mantissa bits (low 13 zeroed) — valid tf32.
__device__ __forceinline__ uint32 tf32hi(float x) {
    return __float_as_uint(x) & 0xFFFFE000u;
}
// m16n8k8 tf32 MMA, D/C fp32 (registers). Legacy HMMA path — no tcgen05.
__device__ __forceinline__ void mma_tf32(float& d0, float& d1, float& d2, float& d3,
                                         uint32 a0, uint32 a1, uint32 a2, uint32 a3,
                                         uint32 b0, uint32 b1) {
    asm volatile(
        "mma.sync.aligned.m16n8k8.row.col.f32.tf32.tf32.f32 "
        "{%0,%1,%2,%3}, {%4,%5,%6,%7}, {%8,%9}, {%0,%1,%2,%3};"
        : "+f"(d0), "+f"(d1), "+f"(d2), "+f"(d3)
        : "r"(a0), "r"(a1), "r"(a2), "r"(a3), "r"(b0), "r"(b1));
}

// ---- dummy first launch: keeps hot layer-3 edge kernel at ncu capture index 5 ----
__global__ void warm_kernel() {}

// ---- layer 1 edge: in_c = 1. One warp per edge. Also counts degree. ----
__global__ void edge1_kernel(const float* __restrict__ x,
                             const int* __restrict__ ei,
                             const float* __restrict__ ea,
                             const float* __restrict__ W1,
                             const float* __restrict__ b1) {
    int gid  = blockIdx.x * blockDim.x + threadIdx.x;
    int e    = gid >> 5;
    int lane = gid & 31;
    if (e >= NE) return;
    float aval = (lane < NVIEWS) ? ea[e * NVIEWS + lane] : 0.f;
    int src = ei[e];
    int dst = ei[NE + e];
    float xs = __ldg(&x[src]);
    float wr = __ldg(&b1[lane]);
#pragma unroll
    for (int v = 0; v < NVIEWS; v++)
        wr = fmaf(__shfl_sync(0xffffffffu, aval, v), __ldg(&W1[v * C + lane]), wr);
    atomicAdd(&g_agg[dst * C + lane], xs * fmaxf(wr, 0.f));
    if (lane == 0) atomicAdd(&g_cnt[dst], 1);
}

// ---- node update 1 + stash inv + restore zeros ----
__global__ void node1_kernel(const float* __restrict__ x,
                             const float* __restrict__ root1,
                             const float* __restrict__ bias1) {
    int idx = blockIdx.x * blockDim.x + threadIdx.x;
    int n = idx >> 5, o = idx & 31;
    float inv = 1.f / fmaxf((float)g_cnt[n], 1.f);
    float v = fmaf(g_agg[idx], inv, fmaf(x[n], root1[o], bias1[o]));
    g_h1[idx] = fmaxf(v, 0.f);
    g_agg[idx] = 0.f;
    if (o == 0) { g_inv[n] = inv; g_cnt[n] = 0; }
}

// ============================================================================
// Tensor-core heavy edge layer via legacy mma.sync (tf32 m16n8k8, HMMA).
// Per 128-edge chunk: w[e, c=i*32+o] = ea@W + b computed as D[16e x 8c] tiles,
// K=8 (6 views + bias slot with A=1.0 + zero pad). fp32 accuracy via tf32
// hi/lo split: D = Ahi*Bhi + Ahi*Blo + Alo*Bhi (err ~2^-20).
// Epilogue per tile: relu(D) weighted by h[src, i=c>>5] from smem, acc in
// regs (o = 8*(k&3)+2q+b per lane), quad-local atomic scatter.
// W hi/lo pre-staged in smem in EXACT fragment order (one LDS.64 per frag).
// Persistent: 256 blocks (2/SM), 256 threads (8 warps x 16 edges).
// ============================================================================
#define EMM_GRID   256
#define EMM_CHUNKS (NE / 128)   // 512
// dyn smem (floats): Bs_hi[128*64] | Bs_lo[128*64] | hsm[32*132]
#define OFF_BH 0
#define OFF_BL (128 * 64)
#define OFF_HS (2 * 128 * 64)
#define EMM_SMEM ((2 * 128 * 64 + 32 * 132) * 4)

__global__ __launch_bounds__(256, 2)
void edge_mma_kernel(int hin_sel,
                     const int* __restrict__ ei,
                     const float* __restrict__ ea,
                     const float* __restrict__ W,
                     const float* __restrict__ b) {
    extern __shared__ float sm[];
    float* Bh  = sm + OFF_BH;
    float* Bl  = sm + OFF_BL;
    float* hsm = sm + OFF_HS;

    int tid = threadIdx.x, lane = tid & 31, w = tid >> 5;
    int g = lane >> 2, q = lane & 3;

    // ---- fill B fragments once per block ----
    // frag spec m16n8k8 B (col): b0 = B[k=q][n=g], b1 = B[k=q+4][n=g]
    for (int idx = tid; idx < 128 * 32; idx += 256) {
        int tile = idx >> 5, l = idx & 31;
        int lq = l & 3, lg = l >> 2;
        int c = tile * 8 + lg;
        float v0 = W[lq * 1024 + c];                         // k = lq (0..3)
        int k1 = lq + 4;
        float v1 = (k1 < 6) ? W[k1 * 1024 + c]
                            : (k1 == 6 ? b[c] : 0.f);        // k = 4..7
        float h0 = __uint_as_float(tf32hi(v0));
        float h1 = __uint_as_float(tf32hi(v1));
        Bh[idx * 2 + 0] = h0;
        Bh[idx * 2 + 1] = h1;
        Bl[idx * 2 + 0] = __uint_as_float(tf32hi(v0 - h0));
        Bl[idx * 2 + 1] = __uint_as_float(tf32hi(v1 - h1));
    }
    __syncthreads();

    const float* __restrict__ h = (hin_sel == 1) ? g_h1 : g_h2;

    for (int chunk = blockIdx.x; chunk < EMM_CHUNKS; chunk += EMM_GRID) {
        int cb = chunk * 128;

        // ---- stage hsm[i][e] (stride 132): thread t -> edge t/2, i-half t&1 ----
        {
            int e = tid >> 1;
            int i0 = (tid & 1) * 16;
            int s = ei[cb + e];
            const float4* hp = (const float4*)&h[s * C + i0];
#pragma unroll
            for (int j4 = 0; j4 < 4; j4++) {
                float4 hv = hp[j4];
                hsm[(i0 + j4 * 4 + 0) * 132 + e] = hv.x;
                hsm[(i0 + j4 * 4 + 1) * 132 + e] = hv.y;
                hsm[(i0 + j4 * 4 + 2) * 132 + e] = hv.z;
                hsm[(i0 + j4 * 4 + 3) * 132 + e] = hv.w;
            }
        }

        // ---- A fragments for this warp's 16 edges ----
        // a0: row g col q | a1: row g+8 col q | a2: row g col q+4 | a3: row g+8 col q+4
        int e0 = cb + (w << 4) + g;
        float a0f = ea[e0 * NVIEWS + q];
        float a1f = ea[(e0 + 8) * NVIEWS + q];
        int v2 = q + 4;
        float a2f = (v2 < 6) ? ea[e0 * NVIEWS + v2]       : (v2 == 6 ? 1.f : 0.f);
        float a3f = (v2 < 6) ? ea[(e0 + 8) * NVIEWS + v2] : (v2 == 6 ? 1.f : 0.f);
        uint32 ah0 = tf32hi(a0f), ah1 = tf32hi(a1f), ah2 = tf32hi(a2f), ah3 = tf32hi(a3f);
        uint32 al0 = tf32hi(a0f - __uint_as_float(ah0));
        uint32 al1 = tf32hi(a1f - __uint_as_float(ah1));
        uint32 al2 = tf32hi(a2f - __uint_as_float(ah2));
        uint32 al3 = tf32hi(a3f - __uint_as_float(ah3));

        __syncthreads();   // hsm ready

        float acc[2][8];
#pragma unroll
        for (int r = 0; r < 2; r++)
#pragma unroll
            for (int o = 0; o < 8; o++) acc[r][o] = 0.f;

        int eb = (w << 4) + g;   // local edge row for hsm
#pragma unroll 1
        for (int k4 = 0; k4 < 32; k4++) {
            float hv0 = hsm[k4 * 132 + eb];
            float hv1 = hsm[k4 * 132 + eb + 8];
#pragma unroll
            for (int m = 0; m < 4; m++) {
                int k = k4 * 4 + m;
                const float2 bhf = *(const float2*)&Bh[(k * 32 + lane) * 2];
                const float2 blf = *(const float2*)&Bl[(k * 32 + lane) * 2];
                uint32 bh0 = __float_as_uint(bhf.x), bh1 = __float_as_uint(bhf.y);
                uint32 bl0 = __float_as_uint(blf.x), bl1 = __float_as_uint(blf.y);
                float d0 = 0.f, d1 = 0.f, d2 = 0.f, d3 = 0.f;
                mma_tf32(d0, d1, d2, d3, ah0, ah1, ah2, ah3, bh0, bh1);
                mma_tf32(d0, d1, d2, d3, ah0, ah1, ah2, ah3, bl0, bl1);
                mma_tf32(d0, d1, d2, d3, al0, al1, al2, al3, bh0, bh1);
                acc[0][m * 2 + 0] = fmaf(hv0, fmaxf(d0, 0.f), acc[0][m * 2 + 0]);
                acc[0][m * 2 + 1] = fmaf(hv0, fmaxf(d1, 0.f), acc[0][m * 2 + 1]);
                acc[1][m * 2 + 0] = fmaf(hv1, fmaxf(d2, 0.f), acc[1][m * 2 + 0]);
                acc[1][m * 2 + 1] = fmaf(hv1, fmaxf(d3, 0.f), acc[1][m * 2 + 1]);
            }
        }

        // ---- scatter: lane covers o = 8m + 2q + b for rows e0, e0+8 ----
        int d0i = ei[NE + e0];
        int d1i = ei[NE + e0 + 8];
#pragma unroll
        for (int m = 0; m < 4; m++) {
#pragma unroll
            for (int bb = 0; bb < 2; bb++) {
                int o = 8 * m + 2 * q + bb;
                atomicAdd(&g_agg[d0i * C + o], acc[0][m * 2 + bb]);
                atomicAdd(&g_agg[d1i * C + o], acc[1][m * 2 + bb]);
            }
        }
        __syncthreads();   // all reads of hsm done before next chunk refill
    }
}

// ---- node update 2/3: warp per node, root via L1 (no smem/sync). ----
__global__ void nodeM_kernel(int sel,
                             const float* __restrict__ root,
                             const float* __restrict__ bias) {
    const float* __restrict__ hin = (sel == 1) ? g_h1 : g_h2;
    float* __restrict__ hout      = (sel == 1) ? g_h2 : g_h3;

    int warp = (blockIdx.x * blockDim.x + threadIdx.x) >> 5;
    int lane = threadIdx.x & 31;
    if (warp >= NN) return;
    int idx = warp * C + lane;
    float hval = hin[idx];
    float acc  = fmaf(g_agg[idx], g_inv[warp], __ldg(&bias[lane]));
    g_agg[idx] = 0.f;
#pragma unroll
    for (int i = 0; i < C; i++)
        acc = fmaf(__shfl_sync(0xffffffffu, hval, i),
                   __ldg(&root[(i << 5) + lane]), acc);
    hout[idx] = fmaxf(acc, 0.f);
}

// ---- CBT: all-pairs L1. Block tile 64(i) x 128(j); thread = 4i x 8j.
// smem row stride 34 ull -> LDS.128 loads 2 k's per instr. ----
__global__ __launch_bounds__(256)
void cbt_kernel(float* __restrict__ out) {
    __shared__ __align__(16) ull hiD[64 * 34];
    __shared__ __align__(16) ull hjN[64 * 34];
    int tid = threadIdx.x, lane = tid & 31, wrow = tid >> 5;
    int i0 = blockIdx.y * 64, j0 = blockIdx.x * 128;

#pragma unroll
    for (int r = 0; r < 8; r++) {
        int n = wrow * 8 + r;
        float v = g_h3[(i0 + n) * C + lane];
        hiD[n * 34 + lane] = pk(v, v);
    }
    float* fj = (float*)hjN;
#pragma unroll
    for (int r = 0; r < 16; r++) {
        int n = wrow * 16 + r;
        float v = g_h3[(j0 + n) * C + lane];
        fj[2 * ((n >> 1) * 34 + lane) + (n & 1)] = -v;
    }
    __syncthreads();

    int tx = tid & 15;
    int ty = tid >> 4;
    ull acc2[4][4];
#pragma unroll
    for (int aa = 0; aa < 4; aa++)
#pragma unroll
        for (int jj = 0; jj < 4; jj++) acc2[aa][jj] = 0ull;

#pragma unroll 4
    for (int kp = 0; kp < 16; kp++) {
        ulonglong2 aj[4];
#pragma unroll
        for (int jj = 0; jj < 4; jj++)
            aj[jj] = *(const ulonglong2*)&hjN[(tx + 16 * jj) * 34 + 2 * kp];
#pragma unroll
        for (int aa = 0; aa < 4; aa++) {
            ulonglong2 ai = *(const ulonglong2*)&hiD[(ty * 4 + aa) * 34 + 2 * kp];
#pragma unroll
            for (int jj = 0; jj < 4; jj++) {
                ull d0 = add2(ai.x, aj[jj].x) & ABSMASK;
                acc2[aa][jj] = add2(acc2[aa][jj], d0);
                ull d1 = add2(ai.y, aj[jj].y) & ABSMASK;
                acc2[aa][jj] = add2(acc2[aa][jj], d1);
            }
        }
    }
#pragma unroll
    for (int aa = 0; aa < 4; aa++) {
        size_t row = (size_t)(i0 + ty * 4 + aa) * NN;
#pragma unroll
        for (int jj = 0; jj < 4; jj++) {
            float lo, hi; upk(acc2[aa][jj], lo, hi);
            *(float2*)&out[row + j0 + 2 * (tx + 16 * jj)] = make_float2(lo, hi);
        }
    }
}

extern "C" void kernel_launch(void* const* d_in, const int* in_sizes, int n_in,
                              void* d_out, int out_size) {
    const float* x     = (const float*)d_in[0];
    const float* ea    = (const float*)d_in[1];
    const int*   ei    = (const int*)d_in[2];
    const float* W1    = (const float*)d_in[3];
    const float* b1    = (const float*)d_in[4];
    const float* root1 = (const float*)d_in[5];
    const float* bias1 = (const float*)d_in[6];
    const float* W2    = (const float*)d_in[7];
    const float* b2    = (const float*)d_in[8];
    const float* root2 = (const float*)d_in[9];
    const float* bias2 = (const float*)d_in[10];
    const float* W3    = (const float*)d_in[11];
    const float* b3    = (const float*)d_in[12];
    const float* root3 = (const float*)d_in[13];
    const float* bias3 = (const float*)d_in[14];
    float* out = (float*)d_out;

    cudaFuncSetAttribute(edge_mma_kernel,
                         cudaFuncAttributeMaxDynamicSharedMemorySize, EMM_SMEM);

    // idx 0 (keeps ncu -s 5 on layer-3 edge kernel)
    warm_kernel<<<1, 32>>>();
    // idx 1,2
    edge1_kernel<<<(NE * 32) / 256, 256>>>(x, ei, ea, W1, b1);
    node1_kernel<<<(NN * C) / 256, 256>>>(x, root1, bias1);
    // layer 2: idx 3,4
    edge_mma_kernel<<<EMM_GRID, 256, EMM_SMEM>>>(1, ei, ea, W2, b2);
    nodeM_kernel<<<(NN * 32) / 256, 256>>>(1, root2, bias2);
    // layer 3: idx 5 (ncu capture), 6
    edge_mma_kernel<<<EMM_GRID, 256, EMM_SMEM>>>(2, ei, ea, W3, b3);
    nodeM_kernel<<<(NN * 32) / 256, 256>>>(2, root3, bias3);
    // CBT: idx 7
    cbt_kernel<<<dim3(NN / 128, NN / 64), 256>>>(out);
}